// round 2
// baseline (speedup 1.0000x reference)
#include <cuda_runtime.h>
#include <math.h>

// ---------------- problem constants ----------------
#define BSZ   1024
#define OC    96
#define DW    200          // d_embd
#define HW    400          // 20*20
#define NENT  40000
#define NFC   115200       // 3*96*400
#define EPSB  1e-5f
#define SPLITK1 20
#define CHUNK1  (NFC / SPLITK1)   // 5760

// ---------------- device scratch (no runtime alloc allowed) ----------------
__device__ float g_x[BSZ * HW];             // permuted raw input
__device__ float g_bn0[2];                  // sum, sumsq
__device__ float g_y[3L * BSZ * OC * HW];   // raw conv outputs, 472 MB
__device__ float g_bsum[3 * BSZ * OC];      // per-(branch,b,oc) sum over HW
__device__ float g_chsum[3 * OC];
__device__ float g_chsq[3 * OC];
__device__ float g_alpha[3 * OC];           // per-branch-channel BN affine
__device__ float g_beta[3 * OC];
__device__ float g_scale[3 * BSZ * OC];     // SE * ATT combined gate
__device__ float g_A[(long)BSZ * NFC];      // activation fed to FC, 472 MB
__device__ float g_c1p[SPLITK1 * BSZ * DW]; // split-K partials
__device__ float g_c1[BSZ * DW];
__device__ float g_z[BSZ * DW];

// ---------------- kernel 0: zero the atomic accumulators ----------------
__global__ void zero_stats() {
    int t = threadIdx.x;
    if (t < 2) g_bn0[t] = 0.f;
    if (t < 3 * OC) { g_chsum[t] = 0.f; g_chsq[t] = 0.f; }
}

// ---------------- kernel 1: gather + chequer permute + BN0 stats ----------------
__global__ void __launch_bounds__(128) gather_bn0(
    const float* __restrict__ n_feats, const float* __restrict__ r_feats,
    const int* __restrict__ sub, const int* __restrict__ rel)
{
    int b = blockIdx.x, t = threadIdx.x;
    int sb = sub[b], rb = rel[b];
    float s = 0.f, q = 0.f;
    for (int i = t; i < HW; i += 128) {
        float v = (i & 1) ? r_feats[rb * DW + (i >> 1)]
                          : n_feats[sb * DW + (i >> 1)];
        g_x[b * HW + i] = v;
        s += v; q += v * v;
    }
    __shared__ float ss[128], sq[128];
    ss[t] = s; sq[t] = q; __syncthreads();
    for (int st = 64; st > 0; st >>= 1) {
        if (t < st) { ss[t] += ss[t + st]; sq[t] += sq[t + st]; }
        __syncthreads();
    }
    if (t == 0) { atomicAdd(&g_bn0[0], ss[0]); atomicAdd(&g_bn0[1], sq[0]); }
}

// ---------------- kernel 2: dynamic grouped convs (3 branches) ----------------
__global__ void __launch_bounds__(384) conv3(
    const float* __restrict__ f1, const float* __restrict__ f2,
    const float* __restrict__ f3, const int* __restrict__ rel,
    const float* __restrict__ bn0g, const float* __restrict__ bn0b)
{
    __shared__ float xs[HW];
    __shared__ float fs[OC * 9];
    int b = blockIdx.x, brch = blockIdx.y, t = threadIdx.x;

    float N0 = (float)BSZ * HW;
    float mean = g_bn0[0] / N0;
    float var  = g_bn0[1] / N0 - mean * mean;
    float a0 = bn0g[0] * rsqrtf(var + EPSB);
    float b0 = bn0b[0] - mean * a0;

    for (int i = t; i < HW; i += 384) xs[i] = g_x[b * HW + i] * a0 + b0;

    int rb = rel[b];
    int flen = (brch == 1) ? OC * 9 : OC * 5;
    const float* fp = (brch == 0 ? f1 : (brch == 1 ? f2 : f3)) + (long)rb * flen;
    for (int i = t; i < flen; i += 384) fs[i] = fp[i];
    __syncthreads();

    int oc = t >> 2, q = t & 3;
    float lsum = 0.f, lsq = 0.f;
    float* yout = g_y + ((long)(brch * BSZ + b) * OC + oc) * HW;

    if (brch == 0) {                       // 1x5, pad W=2
        const float* fo = &fs[oc * 5];
        float k0 = fo[0], k1 = fo[1], k2 = fo[2], k3 = fo[3], k4 = fo[4];
        for (int p = q * 100; p < q * 100 + 100; p++) {
            int h = p / 20, w = p - h * 20;
            const float* xr = &xs[h * 20];
            float acc = xr[w] * k2;
            if (w >= 2)  acc += xr[w - 2] * k0;
            if (w >= 1)  acc += xr[w - 1] * k1;
            if (w <= 18) acc += xr[w + 1] * k3;
            if (w <= 17) acc += xr[w + 2] * k4;
            yout[p] = acc; lsum += acc; lsq += acc * acc;
        }
    } else if (brch == 1) {                // 3x3, pad 1
        const float* fo = &fs[oc * 9];
        float k[9];
        #pragma unroll
        for (int i = 0; i < 9; i++) k[i] = fo[i];
        for (int p = q * 100; p < q * 100 + 100; p++) {
            int h = p / 20, w = p - h * 20;
            float acc = 0.f;
            #pragma unroll
            for (int dh = 0; dh < 3; dh++) {
                int hh = h + dh - 1;
                if (hh < 0 || hh >= 20) continue;
                const float* xr = &xs[hh * 20];
                #pragma unroll
                for (int dw = 0; dw < 3; dw++) {
                    int ww = w + dw - 1;
                    if (ww >= 0 && ww < 20) acc += xr[ww] * k[dh * 3 + dw];
                }
            }
            yout[p] = acc; lsum += acc; lsq += acc * acc;
        }
    } else {                               // 5x1, pad H=2
        const float* fo = &fs[oc * 5];
        float k[5];
        #pragma unroll
        for (int i = 0; i < 5; i++) k[i] = fo[i];
        for (int p = q * 100; p < q * 100 + 100; p++) {
            int h = p / 20, w = p - h * 20;
            float acc = 0.f;
            #pragma unroll
            for (int dh = 0; dh < 5; dh++) {
                int hh = h + dh - 2;
                if (hh >= 0 && hh < 20) acc += xs[hh * 20 + w] * k[dh];
            }
            yout[p] = acc; lsum += acc; lsq += acc * acc;
        }
    }

    // reduce across the 4 threads of this oc (lane-aligned groups of 4)
    lsum += __shfl_down_sync(0xffffffffu, lsum, 2, 4);
    lsum += __shfl_down_sync(0xffffffffu, lsum, 1, 4);
    lsq  += __shfl_down_sync(0xffffffffu, lsq, 2, 4);
    lsq  += __shfl_down_sync(0xffffffffu, lsq, 1, 4);
    if (q == 0) {
        g_bsum[(brch * BSZ + b) * OC + oc] = lsum;
        atomicAdd(&g_chsum[brch * OC + oc], lsum);
        atomicAdd(&g_chsq[brch * OC + oc], lsq);
    }
}

// ---------------- kernel 3: per-branch-channel BN affine ----------------
__global__ void bnaff(
    const float* __restrict__ g1, const float* __restrict__ b1,
    const float* __restrict__ g2, const float* __restrict__ b2,
    const float* __restrict__ g3, const float* __restrict__ b3)
{
    int i = threadIdx.x;
    if (i < 3 * OC) {
        int brch = i / OC, c = i - brch * OC;
        float N = (float)BSZ * HW;
        float mean = g_chsum[i] / N;
        float var  = g_chsq[i] / N - mean * mean;
        const float* g = brch == 0 ? g1 : (brch == 1 ? g2 : g3);
        const float* bb = brch == 0 ? b1 : (brch == 1 ? b2 : b3);
        float a = g[c] * rsqrtf(var + EPSB);
        g_alpha[i] = a;
        g_beta[i]  = bb[c] - mean * a;
    }
}

// ---------------- reductions over 128 threads ----------------
__device__ __forceinline__ float redsum128(float v, float* sm) {
    int t = threadIdx.x;
    sm[t] = v; __syncthreads();
    for (int s = 64; s > 0; s >>= 1) {
        if (t < s) sm[t] += sm[t + s];
        __syncthreads();
    }
    float r = sm[0]; __syncthreads();
    return r;
}
__device__ __forceinline__ float redmax128(float v, float* sm) {
    int t = threadIdx.x;
    sm[t] = v; __syncthreads();
    for (int s = 64; s > 0; s >>= 1) {
        if (t < s) sm[t] = fmaxf(sm[t], sm[t + s]);
        __syncthreads();
    }
    float r = sm[0]; __syncthreads();
    return r;
}

// ---------------- kernel 4: SE + ATT gates (all on (B,96) pools) ----------------
__global__ void __launch_bounds__(128) gates(
    const float* __restrict__ s1w1, const float* __restrict__ s1w2,
    const float* __restrict__ s2w1, const float* __restrict__ s2w2,
    const float* __restrict__ s3w1, const float* __restrict__ s3w2,
    const float* __restrict__ aw1, const float* __restrict__ aw2)
{
    __shared__ float sm[128];
    int b = blockIdx.x, t = threadIdx.x;
    bool act = t < OC;
    int oc = act ? t : 0;

    const float* w1s[3] = {s1w1, s2w1, s3w1};
    const float* w2s[3] = {s1w2, s2w2, s3w2};

    float pool[3], seg[3];
    #pragma unroll
    for (int br = 0; br < 3; br++) {
        float p = fmaf(g_alpha[br * OC + oc],
                       g_bsum[(br * BSZ + b) * OC + oc] * (1.f / HW),
                       g_beta[br * OC + oc]);
        pool[br] = act ? p : 0.f;
    }
    #pragma unroll
    for (int br = 0; br < 3; br++) {
        float h0 = redsum128(act ? pool[br] * w1s[br][oc] : 0.f, sm);
        float h1 = redsum128(act ? pool[br] * w1s[br][OC + oc] : 0.f, sm);
        h0 = fmaxf(h0, 0.f); h1 = fmaxf(h1, 0.f);
        float lg = h0 * w2s[br][oc * 2] + h1 * w2s[br][oc * 2 + 1];
        seg[br] = 1.f / (1.f + expf(-lg));
    }
    float attp = seg[0] * pool[0] + seg[1] * pool[1] + seg[2] * pool[2];
    float a0 = fmaxf(redsum128(act ? attp * aw1[oc] : 0.f, sm), 0.f);
    float a1 = fmaxf(redsum128(act ? attp * aw1[OC + oc] : 0.f, sm), 0.f);

    float l[3], mx = -1e30f;
    #pragma unroll
    for (int br = 0; br < 3; br++) {
        l[br] = act ? (a0 * aw2[(br * OC + oc) * 2] + a1 * aw2[(br * OC + oc) * 2 + 1])
                    : -1e30f;
        mx = fmaxf(mx, l[br]);
    }
    float gm = redmax128(mx, sm);
    float e[3], le = 0.f;
    #pragma unroll
    for (int br = 0; br < 3; br++) { e[br] = expf(l[br] - gm); le += e[br]; }
    float S = redsum128(le, sm);
    if (act) {
        #pragma unroll
        for (int br = 0; br < 3; br++)
            g_scale[(br * BSZ + b) * OC + oc] = seg[br] * e[br] / S;
    }
}

// ---------------- kernel 5: build FC input activation ----------------
__global__ void __launch_bounds__(256) buildA() {
    int b = blockIdx.y;
    int j = blockIdx.x * 256 + threadIdx.x;     // 450*256 == 115200 exact
    int brch = j / (OC * HW);
    int rem = j - brch * OC * HW;
    int oc = rem / HW;
    int p = rem - oc * HW;
    float y = g_y[((long)(brch * BSZ + b) * OC + oc) * HW + p];
    float v = fmaf(g_alpha[brch * OC + oc], y, g_beta[brch * OC + oc])
              * g_scale[(brch * BSZ + b) * OC + oc];
    g_A[(long)b * NFC + j] = fmaxf(v, 0.f);
}

// ---------------- shared SIMT NT-GEMM core: C[m,n] = sum_k A[m,k]*B[n,k] ----------------
__device__ __forceinline__ void gemm_core(
    const float* __restrict__ A, int lda,
    const float* __restrict__ Bm, int ldb,
    float* __restrict__ C, int ldc,
    int M, int N, int K, int k0, int kchunk,
    const float* __restrict__ bias)
{
    __shared__ float As[16][128];
    __shared__ float Bs[16][64];
    int tid = threadIdx.x;
    int n0 = blockIdx.x * 64;
    int m0 = blockIdx.y * 128;
    int k1 = min(k0 + kchunk, K);

    float acc[8][4];
    #pragma unroll
    for (int i = 0; i < 8; i++)
        #pragma unroll
        for (int j = 0; j < 4; j++) acc[i][j] = 0.f;

    int ty = tid >> 4, tx = tid & 15;
    int ar = tid >> 1, akc = (tid & 1) * 8;
    int brr = tid >> 2, bkc = (tid & 3) * 4;

    for (int kt = k0; kt < k1; kt += 16) {
        const float* Ap = A + (long)(m0 + ar) * lda + kt + akc;
        #pragma unroll
        for (int j = 0; j < 8; j++) {
            int kk = kt + akc + j;
            As[akc + j][ar] = (kk < k1) ? Ap[j] : 0.f;
        }
        int nb = n0 + brr;
        const float* Bp = Bm + (long)nb * ldb + kt + bkc;
        #pragma unroll
        for (int j = 0; j < 4; j++) {
            int kk = kt + bkc + j;
            Bs[bkc + j][brr] = (nb < N && kk < k1) ? Bp[j] : 0.f;
        }
        __syncthreads();
        #pragma unroll
        for (int kk = 0; kk < 16; kk++) {
            float4 a0 = *(const float4*)&As[kk][ty * 8];
            float4 a1 = *(const float4*)&As[kk][ty * 8 + 4];
            float4 bv = *(const float4*)&Bs[kk][tx * 4];
            float am[8] = {a0.x, a0.y, a0.z, a0.w, a1.x, a1.y, a1.z, a1.w};
            float bn[4] = {bv.x, bv.y, bv.z, bv.w};
            #pragma unroll
            for (int i = 0; i < 8; i++)
                #pragma unroll
                for (int j = 0; j < 4; j++) acc[i][j] += am[i] * bn[j];
        }
        __syncthreads();
    }
    #pragma unroll
    for (int i = 0; i < 8; i++) {
        int m = m0 + ty * 8 + i;
        #pragma unroll
        for (int j = 0; j < 4; j++) {
            int n = n0 + tx * 4 + j;
            if (n < N)
                C[(long)m * ldc + n] = acc[i][j] + (bias ? bias[n] : 0.f);
        }
    }
}

__global__ void __launch_bounds__(256) gemm1_kernel(const float* __restrict__ fcw) {
    float* Cp = g_c1p + (long)blockIdx.z * BSZ * DW;
    gemm_core(g_A, NFC, fcw, NFC, Cp, DW, BSZ, DW, NFC,
              blockIdx.z * CHUNK1, CHUNK1, nullptr);
}

__global__ void __launch_bounds__(256) gemm2_kernel(
    const float* __restrict__ nf, const float* __restrict__ biasb, float* __restrict__ out) {
    gemm_core(g_z, DW, nf, DW, out, NENT, BSZ, NENT, DW, 0, DW, biasb);
}

// ---------------- kernel 6: split-K reduce + fc bias ----------------
__global__ void __launch_bounds__(256) reduce_c1(const float* __restrict__ fcb) {
    int idx = blockIdx.x * 256 + threadIdx.x;     // 800*256 == 204800 exact
    float s = 0.f;
    #pragma unroll
    for (int z = 0; z < SPLITK1; z++) s += g_c1p[z * BSZ * DW + idx];
    g_c1[idx] = s + fcb[idx % DW];
}

// ---------------- kernel 7: BatchNorm1d over batch + ReLU ----------------
__global__ void __launch_bounds__(256) bn2_relu(
    const float* __restrict__ g2, const float* __restrict__ b2) {
    int d = blockIdx.x, t = threadIdx.x;
    float s = 0.f, q = 0.f;
    for (int b = t; b < BSZ; b += 256) {
        float v = g_c1[b * DW + d];
        s += v; q += v * v;
    }
    __shared__ float ss[256], sq[256];
    ss[t] = s; sq[t] = q; __syncthreads();
    for (int st = 128; st > 0; st >>= 1) {
        if (t < st) { ss[t] += ss[t + st]; sq[t] += sq[t + st]; }
        __syncthreads();
    }
    float mean = ss[0] / BSZ;
    float var  = sq[0] / BSZ - mean * mean;
    float a = g2[d] * rsqrtf(var + EPSB);
    float bb = b2[d] - mean * a;
    for (int b = t; b < BSZ; b += 256) {
        float v = g_c1[b * DW + d];
        g_z[b * DW + d] = fmaxf(fmaf(a, v, bb), 0.f);
    }
}

// ---------------- launch ----------------
extern "C" void kernel_launch(void* const* d_in, const int* in_sizes, int n_in,
                              void* d_out, int out_size) {
    const float* n_feats = (const float*)d_in[0];
    const float* r_feats = (const float*)d_in[1];
    const float* filt1   = (const float*)d_in[2];
    const float* filt2   = (const float*)d_in[3];
    const float* filt3   = (const float*)d_in[4];
    const float* bn0_g   = (const float*)d_in[5];
    const float* bn0_b   = (const float*)d_in[6];
    const float* bn1_g   = (const float*)d_in[7];
    const float* bn1_b   = (const float*)d_in[8];
    const float* bn2c_g  = (const float*)d_in[9];
    const float* bn2c_b  = (const float*)d_in[10];
    const float* bn3c_g  = (const float*)d_in[11];
    const float* bn3c_b  = (const float*)d_in[12];
    const float* se1_w1  = (const float*)d_in[13];
    const float* se1_w2  = (const float*)d_in[14];
    const float* se2_w1  = (const float*)d_in[15];
    const float* se2_w2  = (const float*)d_in[16];
    const float* se3_w1  = (const float*)d_in[17];
    const float* se3_w2  = (const float*)d_in[18];
    const float* att_w1  = (const float*)d_in[19];
    const float* att_w2  = (const float*)d_in[20];
    const float* fc_w    = (const float*)d_in[21];
    const float* fc_b    = (const float*)d_in[22];
    const float* bn2_g   = (const float*)d_in[23];
    const float* bn2_b   = (const float*)d_in[24];
    const float* bias_b  = (const float*)d_in[25];
    const int*   sub     = (const int*)d_in[26];
    const int*   rel     = (const int*)d_in[27];

    zero_stats<<<1, 3 * OC>>>();
    gather_bn0<<<BSZ, 128>>>(n_feats, r_feats, sub, rel);
    conv3<<<dim3(BSZ, 3), 384>>>(filt1, filt2, filt3, rel, bn0_g, bn0_b);
    bnaff<<<1, 3 * OC>>>(bn1_g, bn1_b, bn2c_g, bn2c_b, bn3c_g, bn3c_b);
    gates<<<BSZ, 128>>>(se1_w1, se1_w2, se2_w1, se2_w2, se3_w1, se3_w2,
                        att_w1, att_w2);
    buildA<<<dim3(450, BSZ), 256>>>();
    gemm1_kernel<<<dim3((DW + 63) / 64, BSZ / 128, SPLITK1), 256>>>(fc_w);
    reduce_c1<<<800, 256>>>(fc_b);
    bn2_relu<<<DW, 256>>>(bn2_g, bn2_b);
    gemm2_kernel<<<dim3(NENT / 64, BSZ / 128, 1), 256>>>(n_feats, bias_b,
                                                         (float*)d_out);
}

// round 3
// speedup vs baseline: 1.7710x; 1.7710x over previous
#include <cuda_runtime.h>
#include <cuda_bf16.h>
#include <math.h>

// ---------------- problem constants ----------------
#define BSZ   1024
#define OC    96
#define DW    200          // d_embd
#define HW    400          // 20*20
#define NENT  40000
#define NFC   115200       // 3*96*400
#define EPSB  1e-5f
#define SK1   32
#define CHUNK1 (NFC / SK1)  // 3600 -> 225 k-steps of 16
#define KP2   208          // gemm2 K padded to multiple of 16

// ---------------- device scratch ----------------
__device__ float g_x[BSZ * HW];
__device__ float g_bn0[2];
__device__ float g_y[3L * BSZ * OC * HW];   // raw conv outputs
__device__ float g_bsum[3 * BSZ * OC];
__device__ float g_chsum[3 * OC];
__device__ float g_chsq[3 * OC];
__device__ float g_alpha[3 * OC];
__device__ float g_beta[3 * OC];
__device__ float g_scale[3 * BSZ * OC];
__device__ __align__(128) __nv_bfloat16 g_Ah[(long)BSZ * NFC];
__device__ __align__(128) __nv_bfloat16 g_Al[(long)BSZ * NFC];
__device__ __align__(128) __nv_bfloat16 g_Wh[(long)DW * NFC];
__device__ __align__(128) __nv_bfloat16 g_Wl[(long)DW * NFC];
__device__ float g_c1p[SK1 * BSZ * DW];
__device__ float g_c1[BSZ * DW];
__device__ __align__(128) __nv_bfloat16 g_zh[BSZ * KP2];
__device__ __align__(128) __nv_bfloat16 g_zl[BSZ * KP2];
__device__ __align__(128) __nv_bfloat16 g_nh[(long)NENT * KP2];
__device__ __align__(128) __nv_bfloat16 g_nl[(long)NENT * KP2];

// ---------------- kernel 0: zero atomics ----------------
__global__ void zero_stats() {
    int t = threadIdx.x;
    if (t < 2) g_bn0[t] = 0.f;
    if (t < 3 * OC) { g_chsum[t] = 0.f; g_chsq[t] = 0.f; }
}

// ---------------- kernel 1: gather + chequer + BN0 stats ----------------
__global__ void __launch_bounds__(128) gather_bn0(
    const float* __restrict__ n_feats, const float* __restrict__ r_feats,
    const int* __restrict__ sub, const int* __restrict__ rel)
{
    int b = blockIdx.x, t = threadIdx.x;
    int sb = sub[b], rb = rel[b];
    float s = 0.f, q = 0.f;
    for (int i = t; i < HW; i += 128) {
        float v = (i & 1) ? r_feats[rb * DW + (i >> 1)]
                          : n_feats[sb * DW + (i >> 1)];
        g_x[b * HW + i] = v;
        s += v; q += v * v;
    }
    __shared__ float ss[128], sq[128];
    ss[t] = s; sq[t] = q; __syncthreads();
    for (int st = 64; st > 0; st >>= 1) {
        if (t < st) { ss[t] += ss[t + st]; sq[t] += sq[t + st]; }
        __syncthreads();
    }
    if (t == 0) { atomicAdd(&g_bn0[0], ss[0]); atomicAdd(&g_bn0[1], sq[0]); }
}

// ---------------- kernel 2: dynamic grouped convs ----------------
__global__ void __launch_bounds__(384) conv3(
    const float* __restrict__ f1, const float* __restrict__ f2,
    const float* __restrict__ f3, const int* __restrict__ rel,
    const float* __restrict__ bn0g, const float* __restrict__ bn0b)
{
    __shared__ float xs[HW];
    __shared__ float fs[OC * 9];
    int b = blockIdx.x, brch = blockIdx.y, t = threadIdx.x;

    float N0 = (float)BSZ * HW;
    float mean = g_bn0[0] / N0;
    float var  = g_bn0[1] / N0 - mean * mean;
    float a0 = bn0g[0] * rsqrtf(var + EPSB);
    float b0 = bn0b[0] - mean * a0;

    for (int i = t; i < HW; i += 384) xs[i] = g_x[b * HW + i] * a0 + b0;

    int rb = rel[b];
    int flen = (brch == 1) ? OC * 9 : OC * 5;
    const float* fp = (brch == 0 ? f1 : (brch == 1 ? f2 : f3)) + (long)rb * flen;
    for (int i = t; i < flen; i += 384) fs[i] = fp[i];
    __syncthreads();

    int oc = t >> 2, q = t & 3;
    float lsum = 0.f, lsq = 0.f;
    float* yout = g_y + ((long)(brch * BSZ + b) * OC + oc) * HW;

    if (brch == 0) {                       // 1x5
        const float* fo = &fs[oc * 5];
        float k0 = fo[0], k1 = fo[1], k2 = fo[2], k3 = fo[3], k4 = fo[4];
        for (int p = q * 100; p < q * 100 + 100; p++) {
            int h = p / 20, w = p - h * 20;
            const float* xr = &xs[h * 20];
            float acc = xr[w] * k2;
            if (w >= 2)  acc += xr[w - 2] * k0;
            if (w >= 1)  acc += xr[w - 1] * k1;
            if (w <= 18) acc += xr[w + 1] * k3;
            if (w <= 17) acc += xr[w + 2] * k4;
            yout[p] = acc; lsum += acc; lsq += acc * acc;
        }
    } else if (brch == 1) {                // 3x3
        const float* fo = &fs[oc * 9];
        float k[9];
        #pragma unroll
        for (int i = 0; i < 9; i++) k[i] = fo[i];
        for (int p = q * 100; p < q * 100 + 100; p++) {
            int h = p / 20, w = p - h * 20;
            float acc = 0.f;
            #pragma unroll
            for (int dh = 0; dh < 3; dh++) {
                int hh = h + dh - 1;
                if (hh < 0 || hh >= 20) continue;
                const float* xr = &xs[hh * 20];
                #pragma unroll
                for (int dw = 0; dw < 3; dw++) {
                    int ww = w + dw - 1;
                    if (ww >= 0 && ww < 20) acc += xr[ww] * k[dh * 3 + dw];
                }
            }
            yout[p] = acc; lsum += acc; lsq += acc * acc;
        }
    } else {                               // 5x1
        const float* fo = &fs[oc * 5];
        float k[5];
        #pragma unroll
        for (int i = 0; i < 5; i++) k[i] = fo[i];
        for (int p = q * 100; p < q * 100 + 100; p++) {
            int h = p / 20, w = p - h * 20;
            float acc = 0.f;
            #pragma unroll
            for (int dh = 0; dh < 5; dh++) {
                int hh = h + dh - 2;
                if (hh >= 0 && hh < 20) acc += xs[hh * 20 + w] * k[dh];
            }
            yout[p] = acc; lsum += acc; lsq += acc * acc;
        }
    }

    lsum += __shfl_down_sync(0xffffffffu, lsum, 2, 4);
    lsum += __shfl_down_sync(0xffffffffu, lsum, 1, 4);
    lsq  += __shfl_down_sync(0xffffffffu, lsq, 2, 4);
    lsq  += __shfl_down_sync(0xffffffffu, lsq, 1, 4);
    if (q == 0) {
        g_bsum[(brch * BSZ + b) * OC + oc] = lsum;
        atomicAdd(&g_chsum[brch * OC + oc], lsum);
        atomicAdd(&g_chsq[brch * OC + oc], lsq);
    }
}

// ---------------- kernel 3: BN affine per branch-channel ----------------
__global__ void bnaff(
    const float* __restrict__ g1, const float* __restrict__ b1,
    const float* __restrict__ g2, const float* __restrict__ b2,
    const float* __restrict__ g3, const float* __restrict__ b3)
{
    int i = threadIdx.x;
    if (i < 3 * OC) {
        int brch = i / OC, c = i - brch * OC;
        float N = (float)BSZ * HW;
        float mean = g_chsum[i] / N;
        float var  = g_chsq[i] / N - mean * mean;
        const float* g = brch == 0 ? g1 : (brch == 1 ? g2 : g3);
        const float* bb = brch == 0 ? b1 : (brch == 1 ? b2 : b3);
        float a = g[c] * rsqrtf(var + EPSB);
        g_alpha[i] = a;
        g_beta[i]  = bb[c] - mean * a;
    }
}

// ---------------- reductions ----------------
__device__ __forceinline__ float redsum128(float v, float* sm) {
    int t = threadIdx.x;
    sm[t] = v; __syncthreads();
    for (int s = 64; s > 0; s >>= 1) {
        if (t < s) sm[t] += sm[t + s];
        __syncthreads();
    }
    float r = sm[0]; __syncthreads();
    return r;
}
__device__ __forceinline__ float redmax128(float v, float* sm) {
    int t = threadIdx.x;
    sm[t] = v; __syncthreads();
    for (int s = 64; s > 0; s >>= 1) {
        if (t < s) sm[t] = fmaxf(sm[t], sm[t + s]);
        __syncthreads();
    }
    float r = sm[0]; __syncthreads();
    return r;
}

// ---------------- kernel 4: SE + ATT gates ----------------
__global__ void __launch_bounds__(128) gates(
    const float* __restrict__ s1w1, const float* __restrict__ s1w2,
    const float* __restrict__ s2w1, const float* __restrict__ s2w2,
    const float* __restrict__ s3w1, const float* __restrict__ s3w2,
    const float* __restrict__ aw1, const float* __restrict__ aw2)
{
    __shared__ float sm[128];
    int b = blockIdx.x, t = threadIdx.x;
    bool act = t < OC;
    int oc = act ? t : 0;

    const float* w1s[3] = {s1w1, s2w1, s3w1};
    const float* w2s[3] = {s1w2, s2w2, s3w2};

    float pool[3], seg[3];
    #pragma unroll
    for (int br = 0; br < 3; br++) {
        float p = fmaf(g_alpha[br * OC + oc],
                       g_bsum[(br * BSZ + b) * OC + oc] * (1.f / HW),
                       g_beta[br * OC + oc]);
        pool[br] = act ? p : 0.f;
    }
    #pragma unroll
    for (int br = 0; br < 3; br++) {
        float h0 = redsum128(act ? pool[br] * w1s[br][oc] : 0.f, sm);
        float h1 = redsum128(act ? pool[br] * w1s[br][OC + oc] : 0.f, sm);
        h0 = fmaxf(h0, 0.f); h1 = fmaxf(h1, 0.f);
        float lg = h0 * w2s[br][oc * 2] + h1 * w2s[br][oc * 2 + 1];
        seg[br] = 1.f / (1.f + expf(-lg));
    }
    float attp = seg[0] * pool[0] + seg[1] * pool[1] + seg[2] * pool[2];
    float a0 = fmaxf(redsum128(act ? attp * aw1[oc] : 0.f, sm), 0.f);
    float a1 = fmaxf(redsum128(act ? attp * aw1[OC + oc] : 0.f, sm), 0.f);

    float l[3], mx = -1e30f;
    #pragma unroll
    for (int br = 0; br < 3; br++) {
        l[br] = act ? (a0 * aw2[(br * OC + oc) * 2] + a1 * aw2[(br * OC + oc) * 2 + 1])
                    : -1e30f;
        mx = fmaxf(mx, l[br]);
    }
    float gm = redmax128(mx, sm);
    float e[3], le = 0.f;
    #pragma unroll
    for (int br = 0; br < 3; br++) { e[br] = expf(l[br] - gm); le += e[br]; }
    float S = redsum128(le, sm);
    if (act) {
        #pragma unroll
        for (int br = 0; br < 3; br++)
            g_scale[(br * BSZ + b) * OC + oc] = seg[br] * e[br] / S;
    }
}

// ---------------- kernel 5: build FC activation as bf16 hi/lo ----------------
__global__ void __launch_bounds__(256) buildA() {
    int b = blockIdx.y;
    int j = blockIdx.x * 256 + threadIdx.x;     // 450*256 == 115200
    int brch = j / (OC * HW);
    int rem = j - brch * OC * HW;
    int oc = rem / HW;
    int p = rem - oc * HW;
    float y = g_y[((long)(brch * BSZ + b) * OC + oc) * HW + p];
    float v = fmaf(g_alpha[brch * OC + oc], y, g_beta[brch * OC + oc])
              * g_scale[(brch * BSZ + b) * OC + oc];
    v = fmaxf(v, 0.f);
    __nv_bfloat16 h = __float2bfloat16(v);
    long idx = (long)b * NFC + j;
    g_Ah[idx] = h;
    g_Al[idx] = __float2bfloat16(v - __bfloat162float(h));
}

// ---------------- split kernels (inputs -> bf16 hi/lo) ----------------
__global__ void __launch_bounds__(256) splitW(const float* __restrict__ w) {
    long i = (long)blockIdx.x * 256 + threadIdx.x;   // 90000*256 == 200*115200
    float v = w[i];
    __nv_bfloat16 h = __float2bfloat16(v);
    g_Wh[i] = h;
    g_Wl[i] = __float2bfloat16(v - __bfloat162float(h));
}

__global__ void __launch_bounds__(256) splitN(const float* __restrict__ nf) {
    long t = (long)blockIdx.x * 256 + threadIdx.x;   // 32500*256 == 40000*208
    int e = (int)(t / KP2), j = (int)(t - (long)e * KP2);
    float v = (j < DW) ? nf[(long)e * DW + j] : 0.f;
    __nv_bfloat16 h = __float2bfloat16(v);
    g_nh[t] = h;
    g_nl[t] = __float2bfloat16(v - __bfloat162float(h));
}

// ---------------- tensor-core GEMM core (bf16x3, NT) ----------------
__device__ __forceinline__ void ldsm4(unsigned r[4], unsigned addr) {
    asm volatile("ldmatrix.sync.aligned.m8n8.x4.shared.b16 {%0,%1,%2,%3}, [%4];"
        : "=r"(r[0]), "=r"(r[1]), "=r"(r[2]), "=r"(r[3]) : "r"(addr));
}
__device__ __forceinline__ void mma_bf16(float* c, const unsigned* a,
                                         unsigned b0, unsigned b1) {
    asm volatile(
        "mma.sync.aligned.m16n8k16.row.col.f32.bf16.bf16.f32 "
        "{%0,%1,%2,%3}, {%4,%5,%6,%7}, {%8,%9}, {%0,%1,%2,%3};"
        : "+f"(c[0]), "+f"(c[1]), "+f"(c[2]), "+f"(c[3])
        : "r"(a[0]), "r"(a[1]), "r"(a[2]), "r"(a[3]), "r"(b0), "r"(b1));
}
__device__ __forceinline__ void cpa16(unsigned s, const void* g) {
    asm volatile("cp.async.ca.shared.global [%0], [%1], 16;" :: "r"(s), "l"(g));
}
__device__ __forceinline__ void cpa16z(unsigned s, const void* g, int srcsz) {
    asm volatile("cp.async.ca.shared.global [%0], [%1], 16, %2;"
                 :: "r"(s), "l"(g), "r"(srcsz));
}

// block tile 128x128, 8 warps (2 m x 4 n), warp tile 64x32
__device__ __forceinline__ void gemm_tc(
    const __nv_bfloat16* __restrict__ Ah, const __nv_bfloat16* __restrict__ Al, int lda,
    const __nv_bfloat16* __restrict__ Bh, const __nv_bfloat16* __restrict__ Bl, int ldb,
    float* __restrict__ C, long ldc, int Nn,
    int m0, int n0, int k0, int nsteps, const float* __restrict__ bias)
{
    // smem: [buf(2)][plane(4: Ah,Al,Bh,Bl)][128x16 bf16 = 4096B] = 32 KB
    __shared__ __align__(16) char smem[32768];
    unsigned sbase = (unsigned)__cvta_generic_to_shared(smem);
    int tid = threadIdx.x, lane = tid & 31, wid = tid >> 5;
    int wm = (wid >> 2) * 64, wn = (wid & 3) * 32;

    int r = tid >> 1;
    unsigned sw = r * 32 + (tid & 1) * 16;          // within-plane store offset
    const __nv_bfloat16* pAh = Ah + (long)(m0 + r) * lda + k0 + (tid & 1) * 8;
    const __nv_bfloat16* pAl = Al + (long)(m0 + r) * lda + k0 + (tid & 1) * 8;
    const __nv_bfloat16* pBh = Bh + (long)(n0 + r) * ldb + k0 + (tid & 1) * 8;
    const __nv_bfloat16* pBl = Bl + (long)(n0 + r) * ldb + k0 + (tid & 1) * 8;
    int bsz = ((n0 + r) < Nn) ? 16 : 0;

    float acc[4][4][4];
    #pragma unroll
    for (int i = 0; i < 4; i++)
        #pragma unroll
        for (int j = 0; j < 4; j++)
            #pragma unroll
            for (int k = 0; k < 4; k++) acc[i][j][k] = 0.f;

    #define ISSUE(buf, step) do {                                            \
        unsigned so = sbase + (unsigned)(buf) * 16384u + sw;                 \
        cpa16 (so,          pAh + (step) * 16);                              \
        cpa16 (so + 4096u,  pAl + (step) * 16);                              \
        cpa16z(so + 8192u,  pBh + (step) * 16, bsz);                         \
        cpa16z(so + 12288u, pBl + (step) * 16, bsz);                         \
        asm volatile("cp.async.commit_group;");                              \
    } while (0)

    ISSUE(0, 0);

    int lrow = (lane & 15) * 32 + (lane >> 4) * 16;   // ldmatrix per-lane offset

    for (int s = 0; s < nsteps; s++) {
        int buf = s & 1;
        if (s + 1 < nsteps) {
            ISSUE(buf ^ 1, s + 1);
            asm volatile("cp.async.wait_group 1;" ::: "memory");
        } else {
            asm volatile("cp.async.wait_group 0;" ::: "memory");
        }
        __syncthreads();

        unsigned base = sbase + (unsigned)buf * 16384u;
        unsigned ah[4][4], al[4][4], bh[2][4], bl[2][4];
        #pragma unroll
        for (int mt = 0; mt < 4; mt++) {
            unsigned off = (unsigned)(wm + mt * 16) * 32u + lrow;
            ldsm4(ah[mt], base + off);
            ldsm4(al[mt], base + 4096u + off);
        }
        #pragma unroll
        for (int j = 0; j < 2; j++) {
            unsigned off = (unsigned)(wn + j * 16) * 32u + lrow;
            ldsm4(bh[j], base + 8192u + off);
            ldsm4(bl[j], base + 12288u + off);
        }
        #pragma unroll
        for (int mt = 0; mt < 4; mt++) {
            #pragma unroll
            for (int j = 0; j < 2; j++) {
                mma_bf16(acc[mt][2*j],   ah[mt], bh[j][0], bh[j][2]);
                mma_bf16(acc[mt][2*j],   ah[mt], bl[j][0], bl[j][2]);
                mma_bf16(acc[mt][2*j],   al[mt], bh[j][0], bh[j][2]);
                mma_bf16(acc[mt][2*j+1], ah[mt], bh[j][1], bh[j][3]);
                mma_bf16(acc[mt][2*j+1], ah[mt], bl[j][1], bl[j][3]);
                mma_bf16(acc[mt][2*j+1], al[mt], bh[j][1], bh[j][3]);
            }
        }
        __syncthreads();
    }
    #undef ISSUE

    #pragma unroll
    for (int mt = 0; mt < 4; mt++) {
        #pragma unroll
        for (int nt = 0; nt < 4; nt++) {
            int rr = m0 + wm + mt * 16 + (lane >> 2);
            int cc = n0 + wn + nt * 8 + (lane & 3) * 2;
            if (cc < Nn) {   // cc even, Nn even -> cc+1 also valid
                float bv0 = bias ? bias[cc] : 0.f;
                float bv1 = bias ? bias[cc + 1] : 0.f;
                C[(long)rr * ldc + cc]           = acc[mt][nt][0] + bv0;
                C[(long)rr * ldc + cc + 1]       = acc[mt][nt][1] + bv1;
                C[(long)(rr + 8) * ldc + cc]     = acc[mt][nt][2] + bv0;
                C[(long)(rr + 8) * ldc + cc + 1] = acc[mt][nt][3] + bv1;
            }
        }
    }
}

__global__ void __launch_bounds__(256, 1) gemm1_tc() {
    gemm_tc(g_Ah, g_Al, NFC, g_Wh, g_Wl, NFC,
            g_c1p + (long)blockIdx.z * (BSZ * DW), DW, DW,
            blockIdx.y * 128, blockIdx.x * 128,
            blockIdx.z * CHUNK1, CHUNK1 / 16, nullptr);
}

__global__ void __launch_bounds__(256, 1) gemm2_tc(
    const float* __restrict__ biasb, float* __restrict__ out) {
    gemm_tc(g_zh, g_zl, KP2, g_nh, g_nl, KP2,
            out, NENT, NENT,
            blockIdx.y * 128, blockIdx.x * 128, 0, KP2 / 16, biasb);
}

// ---------------- kernel 6: split-K reduce + fc bias ----------------
__global__ void __launch_bounds__(256) reduce_c1(const float* __restrict__ fcb) {
    int idx = blockIdx.x * 256 + threadIdx.x;     // 800*256 == 204800
    float s = 0.f;
    #pragma unroll
    for (int z = 0; z < SK1; z++) s += g_c1p[z * (BSZ * DW) + idx];
    g_c1[idx] = s + fcb[idx % DW];
}

// ---------------- kernel 7: BN1d + ReLU -> bf16 hi/lo (padded) ----------------
__global__ void __launch_bounds__(256) bn2_relu(
    const float* __restrict__ g2, const float* __restrict__ b2) {
    int d = blockIdx.x, t = threadIdx.x;          // d in [0,208)
    if (d >= DW) {
        for (int b = t; b < BSZ; b += 256) {
            g_zh[b * KP2 + d] = __float2bfloat16(0.f);
            g_zl[b * KP2 + d] = __float2bfloat16(0.f);
        }
        return;
    }
    float s = 0.f, q = 0.f;
    for (int b = t; b < BSZ; b += 256) {
        float v = g_c1[b * DW + d];
        s += v; q += v * v;
    }
    __shared__ float ss[256], sq[256];
    ss[t] = s; sq[t] = q; __syncthreads();
    for (int st = 128; st > 0; st >>= 1) {
        if (t < st) { ss[t] += ss[t + st]; sq[t] += sq[t + st]; }
        __syncthreads();
    }
    float mean = ss[0] / BSZ;
    float var  = sq[0] / BSZ - mean * mean;
    float a = g2[d] * rsqrtf(var + EPSB);
    float bb = b2[d] - mean * a;
    for (int b = t; b < BSZ; b += 256) {
        float v = fmaxf(fmaf(a, g_c1[b * DW + d], bb), 0.f);
        __nv_bfloat16 h = __float2bfloat16(v);
        g_zh[b * KP2 + d] = h;
        g_zl[b * KP2 + d] = __float2bfloat16(v - __bfloat162float(h));
    }
}

// ---------------- launch ----------------
extern "C" void kernel_launch(void* const* d_in, const int* in_sizes, int n_in,
                              void* d_out, int out_size) {
    const float* n_feats = (const float*)d_in[0];
    const float* r_feats = (const float*)d_in[1];
    const float* filt1   = (const float*)d_in[2];
    const float* filt2   = (const float*)d_in[3];
    const float* filt3   = (const float*)d_in[4];
    const float* bn0_g   = (const float*)d_in[5];
    const float* bn0_b   = (const float*)d_in[6];
    const float* bn1_g   = (const float*)d_in[7];
    const float* bn1_b   = (const float*)d_in[8];
    const float* bn2c_g  = (const float*)d_in[9];
    const float* bn2c_b  = (const float*)d_in[10];
    const float* bn3c_g  = (const float*)d_in[11];
    const float* bn3c_b  = (const float*)d_in[12];
    const float* se1_w1  = (const float*)d_in[13];
    const float* se1_w2  = (const float*)d_in[14];
    const float* se2_w1  = (const float*)d_in[15];
    const float* se2_w2  = (const float*)d_in[16];
    const float* se3_w1  = (const float*)d_in[17];
    const float* se3_w2  = (const float*)d_in[18];
    const float* att_w1  = (const float*)d_in[19];
    const float* att_w2  = (const float*)d_in[20];
    const float* fc_w    = (const float*)d_in[21];
    const float* fc_b    = (const float*)d_in[22];
    const float* bn2_g   = (const float*)d_in[23];
    const float* bn2_b   = (const float*)d_in[24];
    const float* bias_b  = (const float*)d_in[25];
    const int*   sub     = (const int*)d_in[26];
    const int*   rel     = (const int*)d_in[27];

    zero_stats<<<1, 3 * OC>>>();
    splitW<<<90000, 256>>>(fc_w);
    splitN<<<32500, 256>>>(n_feats);
    gather_bn0<<<BSZ, 128>>>(n_feats, r_feats, sub, rel);
    conv3<<<dim3(BSZ, 3), 384>>>(filt1, filt2, filt3, rel, bn0_g, bn0_b);
    bnaff<<<1, 3 * OC>>>(bn1_g, bn1_b, bn2c_g, bn2c_b, bn3c_g, bn3c_b);
    gates<<<BSZ, 128>>>(se1_w1, se1_w2, se2_w1, se2_w2, se3_w1, se3_w2,
                        att_w1, att_w2);
    buildA<<<dim3(450, BSZ), 256>>>();
    gemm1_tc<<<dim3(2, BSZ / 128, SK1), 256>>>();
    reduce_c1<<<800, 256>>>(fc_b);
    bn2_relu<<<KP2, 256>>>(bn2_g, bn2_b);
    gemm2_tc<<<dim3((NENT + 127) / 128, BSZ / 128), 256>>>(bias_b, (float*)d_out);
}

// round 5
// speedup vs baseline: 2.8997x; 1.6373x over previous
#include <cuda_runtime.h>
#include <cuda_bf16.h>
#include <stdint.h>
#include <math.h>

// ---------------- problem constants ----------------
#define BSZ   1024
#define OC    96
#define DW    200          // d_embd
#define HW    400          // 20*20
#define NENT  40000
#define NFC   115200       // 3*96*400
#define EPSB  1e-5f
#define SK1   32
#define CH1   (NFC / SK1)  // 3600
#define NK1   (CH1 / 16)   // 225
#define KP2   208          // gemm2 K padded to mult of 16
#define NK2   (KP2 / 16)   // 13

// ---------------- device scratch ----------------
__device__ float g_x[BSZ * HW];
__device__ float g_bn0[2];
__device__ float g_bsum[3 * BSZ * OC];
__device__ float g_chsum[3 * OC];
__device__ float g_chsq[3 * OC];
__device__ float g_alpha[3 * OC];
__device__ float g_beta[3 * OC];
__device__ float g_scale[3 * BSZ * OC];
__device__ __align__(128) __nv_bfloat16 g_Ah[(long)BSZ * NFC];
__device__ __align__(128) __nv_bfloat16 g_Al[(long)BSZ * NFC];
__device__ __align__(128) __nv_bfloat16 g_Wh[(long)DW * NFC];
__device__ __align__(128) __nv_bfloat16 g_Wl[(long)DW * NFC];
__device__ float g_c1p[SK1 * BSZ * DW];
__device__ float g_c1[BSZ * DW];
__device__ __align__(128) __nv_bfloat16 g_zh[BSZ * KP2];
__device__ __align__(128) __nv_bfloat16 g_zl[BSZ * KP2];
__device__ __align__(128) __nv_bfloat16 g_nh[(long)NENT * KP2];
__device__ __align__(128) __nv_bfloat16 g_nl[(long)NENT * KP2];

// ---------------- PTX helpers ----------------
__device__ __forceinline__ void ldsm4(unsigned r[4], unsigned addr) {
    asm volatile("ldmatrix.sync.aligned.m8n8.x4.shared.b16 {%0,%1,%2,%3}, [%4];"
        : "=r"(r[0]), "=r"(r[1]), "=r"(r[2]), "=r"(r[3]) : "r"(addr));
}
__device__ __forceinline__ void mma_bf16(float* c, const unsigned* a,
                                         unsigned b0, unsigned b1) {
    asm volatile(
        "mma.sync.aligned.m16n8k16.row.col.f32.bf16.bf16.f32 "
        "{%0,%1,%2,%3}, {%4,%5,%6,%7}, {%8,%9}, {%0,%1,%2,%3};"
        : "+f"(c[0]), "+f"(c[1]), "+f"(c[2]), "+f"(c[3])
        : "r"(a[0]), "r"(a[1]), "r"(a[2]), "r"(a[3]), "r"(b0), "r"(b1));
}
__device__ __forceinline__ void cpa16(unsigned s, const void* g) {
    asm volatile("cp.async.ca.shared.global [%0], [%1], 16;" :: "r"(s), "l"(g));
}
__device__ __forceinline__ void cpa16z(unsigned s, const void* g, int srcsz) {
    asm volatile("cp.async.ca.shared.global [%0], [%1], 16, %2;"
                 :: "r"(s), "l"(g), "r"(srcsz));
}

// ---------------- kernel 0: zero atomics ----------------
__global__ void zero_stats() {
    int t = threadIdx.x;
    if (t < 2) g_bn0[t] = 0.f;
    if (t < 3 * OC) { g_chsum[t] = 0.f; g_chsq[t] = 0.f; }
}

// ---------------- kernel 1: gather + chequer + BN0 stats ----------------
__global__ void __launch_bounds__(128) gather_bn0(
    const float* __restrict__ n_feats, const float* __restrict__ r_feats,
    const int* __restrict__ sub, const int* __restrict__ rel)
{
    int b = blockIdx.x, t = threadIdx.x;
    int sb = sub[b], rb = rel[b];
    float s = 0.f, q = 0.f;
    for (int i = t; i < HW; i += 128) {
        float v = (i & 1) ? r_feats[rb * DW + (i >> 1)]
                          : n_feats[sb * DW + (i >> 1)];
        g_x[b * HW + i] = v;
        s += v; q += v * v;
    }
    __shared__ float ss[128], sq[128];
    ss[t] = s; sq[t] = q; __syncthreads();
    for (int st = 64; st > 0; st >>= 1) {
        if (t < st) { ss[t] += ss[t + st]; sq[t] += sq[t + st]; }
        __syncthreads();
    }
    if (t == 0) { atomicAdd(&g_bn0[0], ss[0]); atomicAdd(&g_bn0[1], sq[0]); }
}

// ---------------- conv helpers ----------------
__device__ __forceinline__ float conv_point(
    const float* __restrict__ xs, const float* __restrict__ fo,
    int brch, int h, int w)
{
    float acc = 0.f;
    if (brch == 0) {
        const float* xr = &xs[h * 20];
        acc = xr[w] * fo[2];
        if (w >= 2)  acc += xr[w - 2] * fo[0];
        if (w >= 1)  acc += xr[w - 1] * fo[1];
        if (w <= 18) acc += xr[w + 1] * fo[3];
        if (w <= 17) acc += xr[w + 2] * fo[4];
    } else if (brch == 1) {
        #pragma unroll
        for (int dh = 0; dh < 3; dh++) {
            int hh = h + dh - 1;
            if (hh < 0 || hh >= 20) continue;
            const float* xr = &xs[hh * 20];
            #pragma unroll
            for (int dw = 0; dw < 3; dw++) {
                int ww = w + dw - 1;
                if (ww >= 0 && ww < 20) acc += xr[ww] * fo[dh * 3 + dw];
            }
        }
    } else {
        #pragma unroll
        for (int dh = 0; dh < 5; dh++) {
            int hh = h + dh - 2;
            if (hh >= 0 && hh < 20) acc += xs[hh * 20 + w] * fo[dh];
        }
    }
    return acc;
}

// ---------------- kernel 2a: conv stats pass (no big writes) ----------------
__global__ void __launch_bounds__(384) conv3_stats(
    const float* __restrict__ f1, const float* __restrict__ f2,
    const float* __restrict__ f3, const int* __restrict__ rel,
    const float* __restrict__ bn0g, const float* __restrict__ bn0b)
{
    __shared__ float xs[HW];
    __shared__ float fs[OC * 9];
    int b = blockIdx.x, brch = blockIdx.y, t = threadIdx.x;

    float N0 = (float)BSZ * HW;
    float mean = g_bn0[0] / N0;
    float var  = g_bn0[1] / N0 - mean * mean;
    float a0 = bn0g[0] * rsqrtf(var + EPSB);
    float b0 = bn0b[0] - mean * a0;

    for (int i = t; i < HW; i += 384) xs[i] = g_x[b * HW + i] * a0 + b0;

    int rb = rel[b];
    int flen = (brch == 1) ? OC * 9 : OC * 5;
    int fstr = (brch == 1) ? 9 : 5;
    const float* fp = (brch == 0 ? f1 : (brch == 1 ? f2 : f3)) + (long)rb * flen;
    for (int i = t; i < flen; i += 384) fs[i] = fp[i];
    __syncthreads();

    int oc = t >> 2, q = t & 3;
    const float* fo = &fs[oc * fstr];
    float lsum = 0.f, lsq = 0.f;
    for (int p = q * 100; p < q * 100 + 100; p++) {
        int h = p / 20, w = p - h * 20;
        float acc = conv_point(xs, fo, brch, h, w);
        lsum += acc; lsq += acc * acc;
    }
    lsum += __shfl_down_sync(0xffffffffu, lsum, 2, 4);
    lsum += __shfl_down_sync(0xffffffffu, lsum, 1, 4);
    lsq  += __shfl_down_sync(0xffffffffu, lsq, 2, 4);
    lsq  += __shfl_down_sync(0xffffffffu, lsq, 1, 4);
    if (q == 0) {
        g_bsum[(brch * BSZ + b) * OC + oc] = lsum;
        atomicAdd(&g_chsum[brch * OC + oc], lsum);
        atomicAdd(&g_chsq[brch * OC + oc], lsq);
    }
}

// ---------------- kernel 3: BN affine per branch-channel ----------------
__global__ void bnaff(
    const float* __restrict__ g1, const float* __restrict__ b1,
    const float* __restrict__ g2, const float* __restrict__ b2,
    const float* __restrict__ g3, const float* __restrict__ b3)
{
    int i = threadIdx.x;
    if (i < 3 * OC) {
        int brch = i / OC, c = i - brch * OC;
        float N = (float)BSZ * HW;
        float mean = g_chsum[i] / N;
        float var  = g_chsq[i] / N - mean * mean;
        const float* g = brch == 0 ? g1 : (brch == 1 ? g2 : g3);
        const float* bb = brch == 0 ? b1 : (brch == 1 ? b2 : b3);
        float a = g[c] * rsqrtf(var + EPSB);
        g_alpha[i] = a;
        g_beta[i]  = bb[c] - mean * a;
    }
}

// ---------------- reductions ----------------
__device__ __forceinline__ float redsum128(float v, float* sm) {
    int t = threadIdx.x;
    sm[t] = v; __syncthreads();
    for (int s = 64; s > 0; s >>= 1) {
        if (t < s) sm[t] += sm[t + s];
        __syncthreads();
    }
    float r = sm[0]; __syncthreads();
    return r;
}
__device__ __forceinline__ float redmax128(float v, float* sm) {
    int t = threadIdx.x;
    sm[t] = v; __syncthreads();
    for (int s = 64; s > 0; s >>= 1) {
        if (t < s) sm[t] = fmaxf(sm[t], sm[t + s]);
        __syncthreads();
    }
    float r = sm[0]; __syncthreads();
    return r;
}

// ---------------- kernel 4: SE + ATT gates ----------------
__global__ void __launch_bounds__(128) gates(
    const float* __restrict__ s1w1, const float* __restrict__ s1w2,
    const float* __restrict__ s2w1, const float* __restrict__ s2w2,
    const float* __restrict__ s3w1, const float* __restrict__ s3w2,
    const float* __restrict__ aw1, const float* __restrict__ aw2)
{
    __shared__ float sm[128];
    int b = blockIdx.x, t = threadIdx.x;
    bool act = t < OC;
    int oc = act ? t : 0;

    const float* w1s[3] = {s1w1, s2w1, s3w1};
    const float* w2s[3] = {s1w2, s2w2, s3w2};

    float pool[3], seg[3];
    #pragma unroll
    for (int br = 0; br < 3; br++) {
        float p = fmaf(g_alpha[br * OC + oc],
                       g_bsum[(br * BSZ + b) * OC + oc] * (1.f / HW),
                       g_beta[br * OC + oc]);
        pool[br] = act ? p : 0.f;
    }
    #pragma unroll
    for (int br = 0; br < 3; br++) {
        float h0 = redsum128(act ? pool[br] * w1s[br][oc] : 0.f, sm);
        float h1 = redsum128(act ? pool[br] * w1s[br][OC + oc] : 0.f, sm);
        h0 = fmaxf(h0, 0.f); h1 = fmaxf(h1, 0.f);
        float lg = h0 * w2s[br][oc * 2] + h1 * w2s[br][oc * 2 + 1];
        seg[br] = 1.f / (1.f + expf(-lg));
    }
    float attp = seg[0] * pool[0] + seg[1] * pool[1] + seg[2] * pool[2];
    float a0 = fmaxf(redsum128(act ? attp * aw1[oc] : 0.f, sm), 0.f);
    float a1 = fmaxf(redsum128(act ? attp * aw1[OC + oc] : 0.f, sm), 0.f);

    float l[3], mx = -1e30f;
    #pragma unroll
    for (int br = 0; br < 3; br++) {
        l[br] = act ? (a0 * aw2[(br * OC + oc) * 2] + a1 * aw2[(br * OC + oc) * 2 + 1])
                    : -1e30f;
        mx = fmaxf(mx, l[br]);
    }
    float gm = redmax128(mx, sm);
    float e[3], le = 0.f;
    #pragma unroll
    for (int br = 0; br < 3; br++) { e[br] = expf(l[br] - gm); le += e[br]; }
    float S = redsum128(le, sm);
    if (act) {
        #pragma unroll
        for (int br = 0; br < 3; br++)
            g_scale[(br * BSZ + b) * OC + oc] = seg[br] * e[br] / S;
    }
}

// ---------------- kernel 2b: conv recompute + gate + relu -> bf16 hi/lo ----------------
__global__ void __launch_bounds__(384) conv3_fused(
    const float* __restrict__ f1, const float* __restrict__ f2,
    const float* __restrict__ f3, const int* __restrict__ rel,
    const float* __restrict__ bn0g, const float* __restrict__ bn0b)
{
    __shared__ float xs[HW];
    __shared__ float fs[OC * 9];
    __shared__ float sA[OC], sBt[OC], sS[OC];
    int b = blockIdx.x, brch = blockIdx.y, t = threadIdx.x;

    float N0 = (float)BSZ * HW;
    float mean = g_bn0[0] / N0;
    float var  = g_bn0[1] / N0 - mean * mean;
    float a0 = bn0g[0] * rsqrtf(var + EPSB);
    float b0 = bn0b[0] - mean * a0;

    for (int i = t; i < HW; i += 384) xs[i] = g_x[b * HW + i] * a0 + b0;

    int rb = rel[b];
    int flen = (brch == 1) ? OC * 9 : OC * 5;
    int fstr = (brch == 1) ? 9 : 5;
    const float* fp = (brch == 0 ? f1 : (brch == 1 ? f2 : f3)) + (long)rb * flen;
    for (int i = t; i < flen; i += 384) fs[i] = fp[i];
    if (t < OC) {
        sA[t]  = g_alpha[brch * OC + t];
        sBt[t] = g_beta[brch * OC + t];
        sS[t]  = g_scale[(brch * BSZ + b) * OC + t];
    }
    __syncthreads();

    long obase = (long)b * NFC + (long)brch * (OC * HW);
    for (int i = t; i < OC * HW; i += 384) {
        int oc = i / HW, p = i - oc * HW;
        int h = p / 20, w = p - h * 20;
        float acc = conv_point(xs, &fs[oc * fstr], brch, h, w);
        float v = fmaxf(fmaf(sA[oc], acc, sBt[oc]) * sS[oc], 0.f);
        __nv_bfloat16 hh = __float2bfloat16(v);
        g_Ah[obase + i] = hh;
        g_Al[obase + i] = __float2bfloat16(v - __bfloat162float(hh));
    }
}

// ---------------- split kernels ----------------
__global__ void __launch_bounds__(256) splitW(const float* __restrict__ w) {
    long i = (long)blockIdx.x * 256 + threadIdx.x;   // 90000 blocks
    float v = w[i];
    __nv_bfloat16 h = __float2bfloat16(v);
    g_Wh[i] = h;
    g_Wl[i] = __float2bfloat16(v - __bfloat162float(h));
}

__global__ void __launch_bounds__(256) splitN(const float* __restrict__ nf) {
    long t = (long)blockIdx.x * 256 + threadIdx.x;   // 32500 blocks
    int e = (int)(t / KP2), j = (int)(t - (long)e * KP2);
    float v = (j < DW) ? nf[(long)e * DW + j] : 0.f;
    __nv_bfloat16 h = __float2bfloat16(v);
    g_nh[t] = h;
    g_nl[t] = __float2bfloat16(v - __bfloat162float(h));
}

// ---------------- HMMA bf16x3 GEMM: 128x128 tile, 3-stage, swizzled ----------------
// smem stage = 4 planes (Ah,Al,Bh,Bl) x [128 rows x 16 k] bf16 (4KB each) = 16KB
__device__ __forceinline__ void gemm_hmma(
    const __nv_bfloat16* __restrict__ Ah, const __nv_bfloat16* __restrict__ Al, long lda,
    const __nv_bfloat16* __restrict__ Bh, const __nv_bfloat16* __restrict__ Bl, long ldb,
    float* __restrict__ C, long ldc, int Nn,
    int m0, int n0, long k0, int nk, const float* __restrict__ bias)
{
    __shared__ __align__(16) char smem[49152];
    unsigned sb = (unsigned)__cvta_generic_to_shared(smem);
    int tid = threadIdx.x, lane = tid & 31, wid = tid >> 5;
    int wm = (wid >> 2) * 64, wn = (wid & 3) * 32;

    float acc[4][4][4];
    #pragma unroll
    for (int i = 0; i < 4; i++)
        #pragma unroll
        for (int j = 0; j < 4; j++)
            #pragma unroll
            for (int k = 0; k < 4; k++) acc[i][j][k] = 0.f;

    #define ISSUE(stg_, kb_) do {                                              \
        unsigned s0_ = sb + (unsigned)(stg_) * 16384u;                         \
        long kk_ = k0 + (long)(kb_) * 16;                                      \
        _Pragma("unroll")                                                      \
        for (int ii = 0; ii < 4; ii++) {                                       \
            int i_ = tid + ii * 256;                                           \
            int pl_ = i_ >> 8, r_ = (i_ >> 1) & 127, c_ = i_ & 1;              \
            unsigned sw_ = s0_ + (unsigned)pl_ * 4096u + (unsigned)r_ * 32u    \
                         + (unsigned)((c_ ^ ((r_ >> 2) & 1)) * 16);            \
            if (pl_ == 0)      cpa16(sw_, Ah + (long)(m0 + r_) * lda + kk_ + c_ * 8); \
            else if (pl_ == 1) cpa16(sw_, Al + (long)(m0 + r_) * lda + kk_ + c_ * 8); \
            else {                                                             \
                int ok_ = ((n0 + r_) < Nn) ? 16 : 0;                           \
                const __nv_bfloat16* P_ = (pl_ == 2) ? Bh : Bl;                \
                cpa16z(sw_, P_ + (long)(n0 + r_) * ldb + kk_ + c_ * 8, ok_);   \
            }                                                                  \
        }                                                                      \
        asm volatile("cp.async.commit_group;" ::: "memory");                   \
    } while (0)

    ISSUE(0, 0);
    ISSUE(1, 1);

    for (int kb = 0; kb < nk; kb++) {
        int st = kb % 3;
        if (kb + 1 < nk)
            asm volatile("cp.async.wait_group 1;" ::: "memory");
        else
            asm volatile("cp.async.wait_group 0;" ::: "memory");
        __syncthreads();

        unsigned s0 = sb + (unsigned)st * 16384u;
        int cbit = lane >> 4;
        unsigned ah[4][4], al[4][4], bh[2][4], bl[2][4];
        #pragma unroll
        for (int mt = 0; mt < 4; mt++) {
            int r = wm + mt * 16 + (lane & 15);
            unsigned off = (unsigned)r * 32u + (unsigned)((cbit ^ ((r >> 2) & 1)) * 16);
            ldsm4(ah[mt], s0 + off);
            ldsm4(al[mt], s0 + 4096u + off);
        }
        #pragma unroll
        for (int j = 0; j < 2; j++) {
            int r = wn + j * 16 + (lane & 15);
            unsigned off = (unsigned)r * 32u + (unsigned)((cbit ^ ((r >> 2) & 1)) * 16);
            ldsm4(bh[j], s0 + 8192u + off);
            ldsm4(bl[j], s0 + 12288u + off);
        }
        #pragma unroll
        for (int mt = 0; mt < 4; mt++) {
            #pragma unroll
            for (int j = 0; j < 2; j++) {
                mma_bf16(acc[mt][2*j],   ah[mt], bh[j][0], bh[j][2]);
                mma_bf16(acc[mt][2*j],   ah[mt], bl[j][0], bl[j][2]);
                mma_bf16(acc[mt][2*j],   al[mt], bh[j][0], bh[j][2]);
                mma_bf16(acc[mt][2*j+1], ah[mt], bh[j][1], bh[j][3]);
                mma_bf16(acc[mt][2*j+1], ah[mt], bl[j][1], bl[j][3]);
                mma_bf16(acc[mt][2*j+1], al[mt], bh[j][1], bh[j][3]);
            }
        }
        if (kb + 2 < nk) ISSUE((kb + 2) % 3, kb + 2);
    }
    #undef ISSUE

    #pragma unroll
    for (int mt = 0; mt < 4; mt++) {
        #pragma unroll
        for (int nt = 0; nt < 4; nt++) {
            int rr = m0 + wm + mt * 16 + (lane >> 2);
            int cc = n0 + wn + nt * 8 + (lane & 3) * 2;
            if (cc < Nn) {   // cc even, Nn even -> cc+1 also valid
                float bv0 = bias ? bias[cc] : 0.f;
                float bv1 = bias ? bias[cc + 1] : 0.f;
                C[(long)rr * ldc + cc]           = acc[mt][nt][0] + bv0;
                C[(long)rr * ldc + cc + 1]       = acc[mt][nt][1] + bv1;
                C[(long)(rr + 8) * ldc + cc]     = acc[mt][nt][2] + bv0;
                C[(long)(rr + 8) * ldc + cc + 1] = acc[mt][nt][3] + bv1;
            }
        }
    }
}

__global__ void __launch_bounds__(256, 1) gemm1_k() {
    gemm_hmma(g_Ah, g_Al, NFC, g_Wh, g_Wl, NFC,
              g_c1p + (long)blockIdx.z * (BSZ * DW), DW, DW,
              blockIdx.y * 128, blockIdx.x * 128,
              (long)blockIdx.z * CH1, NK1, nullptr);
}

__global__ void __launch_bounds__(256, 1) gemm2_k(
    const float* __restrict__ biasb, float* __restrict__ out) {
    gemm_hmma(g_zh, g_zl, KP2, g_nh, g_nl, KP2,
              out, NENT, NENT,
              blockIdx.y * 128, blockIdx.x * 128, 0, NK2, biasb);
}

// ---------------- kernel 6: split-K reduce + fc bias ----------------
__global__ void __launch_bounds__(256) reduce_c1(const float* __restrict__ fcb) {
    int idx = blockIdx.x * 256 + threadIdx.x;     // 800*256 == 204800
    float s = 0.f;
    #pragma unroll
    for (int z = 0; z < SK1; z++) s += g_c1p[z * (BSZ * DW) + idx];
    g_c1[idx] = s + fcb[idx % DW];
}

// ---------------- kernel 7: BN1d + ReLU -> bf16 hi/lo (padded to KP2) ----------------
__global__ void __launch_bounds__(256) bn2_relu(
    const float* __restrict__ g2, const float* __restrict__ b2) {
    int d = blockIdx.x, t = threadIdx.x;          // d in [0,KP2)
    if (d >= DW) {
        for (int b = t; b < BSZ; b += 256) {
            g_zh[b * KP2 + d] = __float2bfloat16(0.f);
            g_zl[b * KP2 + d] = __float2bfloat16(0.f);
        }
        return;
    }
    float s = 0.f, q = 0.f;
    for (int b = t; b < BSZ; b += 256) {
        float v = g_c1[b * DW + d];
        s += v; q += v * v;
    }
    __shared__ float ss[256], sq[256];
    ss[t] = s; sq[t] = q; __syncthreads();
    for (int st = 128; st > 0; st >>= 1) {
        if (t < st) { ss[t] += ss[t + st]; sq[t] += sq[t + st]; }
        __syncthreads();
    }
    float mean = ss[0] / BSZ;
    float var  = sq[0] / BSZ - mean * mean;
    float a = g2[d] * rsqrtf(var + EPSB);
    float bb = b2[d] - mean * a;
    for (int b = t; b < BSZ; b += 256) {
        float v = fmaxf(fmaf(a, g_c1[b * DW + d], bb), 0.f);
        __nv_bfloat16 h = __float2bfloat16(v);
        g_zh[b * KP2 + d] = h;
        g_zl[b * KP2 + d] = __float2bfloat16(v - __bfloat162float(h));
    }
}

// ---------------- launch ----------------
extern "C" void kernel_launch(void* const* d_in, const int* in_sizes, int n_in,
                              void* d_out, int out_size) {
    const float* n_feats = (const float*)d_in[0];
    const float* r_feats = (const float*)d_in[1];
    const float* filt1   = (const float*)d_in[2];
    const float* filt2   = (const float*)d_in[3];
    const float* filt3   = (const float*)d_in[4];
    const float* bn0_g   = (const float*)d_in[5];
    const float* bn0_b   = (const float*)d_in[6];
    const float* bn1_g   = (const float*)d_in[7];
    const float* bn1_b   = (const float*)d_in[8];
    const float* bn2c_g  = (const float*)d_in[9];
    const float* bn2c_b  = (const float*)d_in[10];
    const float* bn3c_g  = (const float*)d_in[11];
    const float* bn3c_b  = (const float*)d_in[12];
    const float* se1_w1  = (const float*)d_in[13];
    const float* se1_w2  = (const float*)d_in[14];
    const float* se2_w1  = (const float*)d_in[15];
    const float* se2_w2  = (const float*)d_in[16];
    const float* se3_w1  = (const float*)d_in[17];
    const float* se3_w2  = (const float*)d_in[18];
    const float* att_w1  = (const float*)d_in[19];
    const float* att_w2  = (const float*)d_in[20];
    const float* fc_w    = (const float*)d_in[21];
    const float* fc_b    = (const float*)d_in[22];
    const float* bn2_g   = (const float*)d_in[23];
    const float* bn2_b   = (const float*)d_in[24];
    const float* bias_b  = (const float*)d_in[25];
    const int*   sub     = (const int*)d_in[26];
    const int*   rel     = (const int*)d_in[27];

    zero_stats<<<1, 3 * OC>>>();
    splitW<<<90000, 256>>>(fc_w);
    splitN<<<32500, 256>>>(n_feats);
    gather_bn0<<<BSZ, 128>>>(n_feats, r_feats, sub, rel);
    conv3_stats<<<dim3(BSZ, 3), 384>>>(filt1, filt2, filt3, rel, bn0_g, bn0_b);
    bnaff<<<1, 3 * OC>>>(bn1_g, bn1_b, bn2c_g, bn2c_b, bn3c_g, bn3c_b);
    gates<<<BSZ, 128>>>(se1_w1, se1_w2, se2_w1, se2_w2, se3_w1, se3_w2,
                        att_w1, att_w2);
    conv3_fused<<<dim3(BSZ, 3), 384>>>(filt1, filt2, filt3, rel, bn0_g, bn0_b);
    gemm1_k<<<dim3(2, BSZ / 128, SK1), 256>>>();
    reduce_c1<<<800, 256>>>(fc_b);
    bn2_relu<<<KP2, 256>>>(bn2_g, bn2_b);
    gemm2_k<<<dim3((NENT + 127) / 128, BSZ / 128), 256>>>(bias_b, (float*)d_out);
}